// round 4
// baseline (speedup 1.0000x reference)
#include <cuda_runtime.h>

#define DD 128
#define NMAX 100000
#define EMAX 1600000

// ---------------- static scratch (no allocations allowed) ----------------
__device__ int   g_cnt[NMAX];          // degree counts, then fill cursor
__device__ int   g_rowptr[NMAX + 1];
__device__ int   g_col[EMAX];
__device__ __align__(16) float g_dinv[NMAX];
__device__ int   g_blocksums[256];
__device__ __align__(16) float g_B1[(size_t)NMAX * DD];   // aggW1 -> aggW2
__device__ __align__(16) float g_B2[(size_t)NMAX * DD];   // aggU1 -> aggU2
__device__ __align__(16) float g_B3[(size_t)NMAX * DD];   // h -> S
__device__ __align__(16) float g_B4[(size_t)NMAX * DD];   // g
__device__ __align__(16) float g_M[DD * DD];              // lin_w @ fc_w
__device__ __align__(16) float g_bfin[DD];                // 2*lin_b@fc_w + fc_b
__device__ __align__(16) float g_bsum[DD];                // gcn_b2 + gin_b2

// Buffer selector so GEMM kernels can reference __device__ symbols directly
// (keeps kernel_launch to pure kernel launches — nothing else under capture).
enum Buf { B1 = 1, B2 = 2, B3 = 3, B4 = 4, BM = 5, BOUT = 6 };

__device__ __forceinline__ float* bufp(int sel, float* out) {
    switch (sel) {
        case B1: return g_B1;
        case B2: return g_B2;
        case B3: return g_B3;
        case B4: return g_B4;
        case BM: return g_M;
        default: return out;
    }
}

// ---------------- CSR build (edge_index is int32 per harness contract) ----------------
__global__ void k_zero_cnt(int n) {
    int i = blockIdx.x * blockDim.x + threadIdx.x;
    if (i < n) g_cnt[i] = 0;
}

__global__ void k_hist(const int* __restrict__ ei, int E, int n) {
    int e = blockIdx.x * blockDim.x + threadIdx.x;
    if (e < E) {
        int d = ei[E + e];
        if (d >= 0 && d < n) atomicAdd(&g_cnt[d], 1);
    }
}

__global__ void k_scan1(int n) {
    __shared__ int s[1024];
    int i = blockIdx.x * 1024 + threadIdx.x;
    int v = (i < n) ? g_cnt[i] : 0;
    s[threadIdx.x] = v;
    __syncthreads();
    for (int off = 1; off < 1024; off <<= 1) {
        int t = (threadIdx.x >= off) ? s[threadIdx.x - off] : 0;
        __syncthreads();
        s[threadIdx.x] += t;
        __syncthreads();
    }
    if (i < n) g_rowptr[i] = s[threadIdx.x] - v;   // exclusive
    if (threadIdx.x == 1023) g_blocksums[blockIdx.x] = s[1023];
}

__global__ void k_scan2(int nb) {
    if (threadIdx.x == 0 && blockIdx.x == 0) {
        int run = 0;
        for (int b = 0; b < nb; b++) {
            int t = g_blocksums[b];
            g_blocksums[b] = run;
            run += t;
        }
    }
}

__global__ void k_scan3(int n, int E) {
    int i = blockIdx.x * blockDim.x + threadIdx.x;
    if (i < n) {
        g_rowptr[i] += g_blocksums[i >> 10];
        g_dinv[i] = rsqrtf((float)g_cnt[i] + 1.0f);
        g_cnt[i] = 0;                       // reuse as fill cursor
    }
    if (i == 0) g_rowptr[n] = E;
}

__global__ void k_fill(const int* __restrict__ ei, int E, int n) {
    int e = blockIdx.x * blockDim.x + threadIdx.x;
    if (e < E) {
        int s = ei[e];
        int d = ei[E + e];
        if (s >= 0 && s < n && d >= 0 && d < n) {
            int pos = g_rowptr[d] + atomicAdd(&g_cnt[d], 1);
            g_col[pos] = s;
        }
    }
}

// ---------------- tiny fused-head precompute ----------------
__global__ void k_mfuse(const float* __restrict__ lin_w, const float* __restrict__ lin_b,
                        const float* __restrict__ fc_w, const float* __restrict__ fc_b,
                        const float* __restrict__ gcn_b2, const float* __restrict__ gin_b2) {
    int c = threadIdx.x;
    if (blockIdx.x < DD) {
        int r = blockIdx.x;
        float a = 0.f;
        #pragma unroll 8
        for (int k = 0; k < DD; k++) a += lin_w[r * DD + k] * fc_w[k * DD + c];
        g_M[r * DD + c] = a;
    } else if (blockIdx.x == DD) {
        float a = 0.f;
        #pragma unroll 8
        for (int k = 0; k < DD; k++) a += lin_b[k] * fc_w[k * DD + c];
        g_bfin[c] = 2.f * a + fc_b[c];
    } else {
        g_bsum[c] = gcn_b2[c] + gin_b2[c];
    }
}

// ---------------- aggregation: warp per node ----------------
// pass 1: weighted(X) -> B1, unweighted(X) -> B2   (shares the X[src] read)
__global__ void k_agg1(const float* __restrict__ X, int n) {
    int w = (blockIdx.x * blockDim.x + threadIdx.x) >> 5;
    if (w >= n) return;
    int lane = threadIdx.x & 31;
    const float4* Xv = (const float4*)X;
    int e = g_rowptr[w], end = g_rowptr[w + 1];
    float4 aw = make_float4(0, 0, 0, 0), au = make_float4(0, 0, 0, 0);
    for (; e < end; e++) {
        int j = g_col[e];
        float dj = g_dinv[j];
        float4 v = Xv[(size_t)j * 32 + lane];
        aw.x += dj * v.x; aw.y += dj * v.y; aw.z += dj * v.z; aw.w += dj * v.w;
        au.x += v.x;      au.y += v.y;      au.z += v.z;      au.w += v.w;
    }
    float di = g_dinv[w];
    float dii = di * di;
    float4 xi = Xv[(size_t)w * 32 + lane];
    float4 ow, ou;
    ow.x = di * aw.x + dii * xi.x; ow.y = di * aw.y + dii * xi.y;
    ow.z = di * aw.z + dii * xi.z; ow.w = di * aw.w + dii * xi.w;
    ou.x = au.x + xi.x; ou.y = au.y + xi.y; ou.z = au.z + xi.z; ou.w = au.w + xi.w;
    ((float4*)g_B1)[(size_t)w * 32 + lane] = ow;
    ((float4*)g_B2)[(size_t)w * 32 + lane] = ou;
}

// pass 2: weighted(B3=h) -> B1, unweighted(B4=g) -> B2
__global__ void k_agg2(int n) {
    int w = (blockIdx.x * blockDim.x + threadIdx.x) >> 5;
    if (w >= n) return;
    int lane = threadIdx.x & 31;
    const float4* Hv = (const float4*)g_B3;
    const float4* Gv = (const float4*)g_B4;
    int e = g_rowptr[w], end = g_rowptr[w + 1];
    float4 aw = make_float4(0, 0, 0, 0), au = make_float4(0, 0, 0, 0);
    for (; e < end; e++) {
        int j = g_col[e];
        float dj = g_dinv[j];
        float4 hv = Hv[(size_t)j * 32 + lane];
        float4 gv = Gv[(size_t)j * 32 + lane];
        aw.x += dj * hv.x; aw.y += dj * hv.y; aw.z += dj * hv.z; aw.w += dj * hv.w;
        au.x += gv.x;      au.y += gv.y;      au.z += gv.z;      au.w += gv.w;
    }
    float di = g_dinv[w];
    float dii = di * di;
    float4 hi = Hv[(size_t)w * 32 + lane];
    float4 gi = Gv[(size_t)w * 32 + lane];
    float4 ow, ou;
    ow.x = di * aw.x + dii * hi.x; ow.y = di * aw.y + dii * hi.y;
    ow.z = di * aw.z + dii * hi.z; ow.w = di * aw.w + dii * hi.w;
    ou.x = au.x + gi.x; ou.y = au.y + gi.y; ou.z = au.z + gi.z; ou.w = au.w + gi.w;
    ((float4*)g_B1)[(size_t)w * 32 + lane] = ow;
    ((float4*)g_B2)[(size_t)w * 32 + lane] = ou;
}

// ---------------- fp32 SGEMM: C[n,128] = A1@W1 (+ A2@W2) + bias, opt relu ----------------
// 128x128 block tile, 256 threads, 8x8 microtile, K chunks of 32.
// A/C buffers and (optionally) W selected by enum so scratch never crosses the
// launch boundary. SELW==BM means "weight lives in g_M"; SELW==0 means "use the
// W1/W2 kernel parameters".
template <bool RELU, int SELA1, int SELA2, int SELC, int SELW>
__launch_bounds__(256)
__global__ void k_gemm(const float* __restrict__ W1, const float* __restrict__ W2,
                       const float* __restrict__ bias, float* __restrict__ outp, int n) {
    __shared__ float As[32 * 128];
    __shared__ float Ws[32 * 128];
    const float* A1 = bufp(SELA1, outp);
    const float* A2 = (SELA2 != 0) ? bufp(SELA2, outp) : nullptr;
    float*       C  = bufp(SELC, outp);
    const float* bias_p = (SELC == B3 && SELA2 != 0) ? g_bsum :
                          (SELC == BOUT)             ? g_bfin : bias;

    int tid = threadIdx.x;
    int row0 = blockIdx.x * 128;
    int tx = tid & 15, ty = tid >> 4;

    float acc[8][8];
    #pragma unroll
    for (int i = 0; i < 8; i++)
        #pragma unroll
        for (int j = 0; j < 8; j++) acc[i][j] = 0.f;

    const int nseg = (SELA2 != 0) ? 2 : 1;
    #pragma unroll
    for (int seg = 0; seg < nseg; seg++) {
        const float* A = seg ? A2 : A1;
        const float* W = (SELW == BM) ? (const float*)g_M : (seg ? W2 : W1);
        for (int kc = 0; kc < 4; kc++) {
            // A tile: 128 rows x 32 k, transposed into As[k][m]
            #pragma unroll
            for (int f = tid; f < 1024; f += 256) {
                int m = f >> 3, kq = f & 7;
                int gr = row0 + m;
                float4 v = (gr < n) ? ((const float4*)A)[(size_t)gr * 32 + kc * 8 + kq]
                                    : make_float4(0, 0, 0, 0);
                int kk = kq * 4;
                As[(kk + 0) * 128 + m] = v.x;
                As[(kk + 1) * 128 + m] = v.y;
                As[(kk + 2) * 128 + m] = v.z;
                As[(kk + 3) * 128 + m] = v.w;
            }
            // W tile: rows kc*32..+31, all 128 cols, natural layout
            #pragma unroll
            for (int f = tid; f < 1024; f += 256) {
                int kk = f >> 5, nq = f & 31;
                ((float4*)Ws)[kk * 32 + nq] = ((const float4*)W)[(size_t)(kc * 32 + kk) * 32 + nq];
            }
            __syncthreads();
            #pragma unroll
            for (int kk = 0; kk < 32; kk++) {
                float4 a0 = *(const float4*)&As[kk * 128 + ty * 4];
                float4 a1 = *(const float4*)&As[kk * 128 + 64 + ty * 4];
                float4 b0 = *(const float4*)&Ws[kk * 128 + tx * 4];
                float4 b1 = *(const float4*)&Ws[kk * 128 + 64 + tx * 4];
                float a[8] = {a0.x, a0.y, a0.z, a0.w, a1.x, a1.y, a1.z, a1.w};
                float b[8] = {b0.x, b0.y, b0.z, b0.w, b1.x, b1.y, b1.z, b1.w};
                #pragma unroll
                for (int i = 0; i < 8; i++)
                    #pragma unroll
                    for (int j = 0; j < 8; j++) acc[i][j] += a[i] * b[j];
            }
            __syncthreads();
        }
    }

    float4 bb0 = ((const float4*)bias_p)[tx];
    float4 bb1 = ((const float4*)bias_p)[16 + tx];
    #pragma unroll
    for (int i = 0; i < 8; i++) {
        int m = (i < 4) ? (ty * 4 + i) : (64 + ty * 4 + (i - 4));
        int gr = row0 + m;
        if (gr >= n) continue;
        float4 o0, o1;
        o0.x = acc[i][0] + bb0.x; o0.y = acc[i][1] + bb0.y;
        o0.z = acc[i][2] + bb0.z; o0.w = acc[i][3] + bb0.w;
        o1.x = acc[i][4] + bb1.x; o1.y = acc[i][5] + bb1.y;
        o1.z = acc[i][6] + bb1.z; o1.w = acc[i][7] + bb1.w;
        if (RELU) {
            o0.x = fmaxf(o0.x, 0.f); o0.y = fmaxf(o0.y, 0.f);
            o0.z = fmaxf(o0.z, 0.f); o0.w = fmaxf(o0.w, 0.f);
            o1.x = fmaxf(o1.x, 0.f); o1.y = fmaxf(o1.y, 0.f);
            o1.z = fmaxf(o1.z, 0.f); o1.w = fmaxf(o1.w, 0.f);
        }
        ((float4*)C)[(size_t)gr * 32 + tx] = o0;
        ((float4*)C)[(size_t)gr * 32 + 16 + tx] = o1;
    }
}

// ---------------- launch ----------------
extern "C" void kernel_launch(void* const* d_in, const int* in_sizes, int n_in,
                              void* d_out, int out_size) {
    const float* X      = (const float*)d_in[0];
    const int*   ei     = (const int*)d_in[1];     // int32 per harness contract
    const float* gcn_w1 = (const float*)d_in[2];
    const float* gcn_b1 = (const float*)d_in[3];
    const float* gcn_w2 = (const float*)d_in[4];
    const float* gcn_b2 = (const float*)d_in[5];
    const float* gin_w1 = (const float*)d_in[6];
    const float* gin_b1 = (const float*)d_in[7];
    const float* gin_w2 = (const float*)d_in[8];
    const float* gin_b2 = (const float*)d_in[9];
    const float* lin_w  = (const float*)d_in[10];
    const float* lin_b  = (const float*)d_in[11];
    const float* fc_w   = (const float*)d_in[12];
    const float* fc_b   = (const float*)d_in[13];
    float*       out    = (float*)d_out;

    int N = in_sizes[0] / DD;
    int E = in_sizes[1] / 2;

    int nb = (N + 1023) / 1024;
    int gN = (N + 255) / 256;
    int gE = (E + 255) / 256;
    int gW = (N + 7) / 8;             // warp-per-node, 8 warps/block
    int gG = (N + 127) / 128;         // gemm blocks

    // CSR build
    k_zero_cnt<<<gN, 256>>>(N);
    k_hist<<<gE, 256>>>(ei, E, N);
    k_scan1<<<nb, 1024>>>(N);
    k_scan2<<<1, 32>>>(nb);
    k_scan3<<<gN, 256>>>(N, E);
    k_fill<<<gE, 256>>>(ei, E, N);

    // tiny head fusion (independent of graph work)
    k_mfuse<<<DD + 2, DD>>>(lin_w, lin_b, fc_w, fc_b, gcn_b2, gin_b2);

    // layer 1: aggregate raw X once for both branches
    k_agg1<<<gW, 256>>>(X, N);
    // h = relu(aggW @ gcn_w1 + gcn_b1)           B1 -> B3
    k_gemm<true,  B1, 0, B3, 0><<<gG, 256>>>(gcn_w1, gcn_w1, gcn_b1, out, N);
    // g = aggU @ gin_w1 + gin_b1                 B2 -> B4
    k_gemm<false, B2, 0, B4, 0><<<gG, 256>>>(gin_w1, gin_w1, gin_b1, out, N);

    // layer 2 aggregation (B3,B4 -> B1,B2)
    k_agg2<<<gW, 256>>>(N);
    // S = aggW2 @ gcn_w2 + aggU2 @ gin_w2 + (gcn_b2+gin_b2)   -> B3  (bias = g_bsum)
    k_gemm<false, B1, B2, B3, 0><<<gG, 256>>>(gcn_w2, gin_w2, gcn_b2, out, N);
    // out = S @ g_M + g_bfin                     (W from symbol: SELW = BM)
    k_gemm<false, B3, 0, BOUT, BM><<<gG, 256>>>(gcn_w2, gcn_w2, gcn_b2, out, N);
}

// round 6
// speedup vs baseline: 1.2113x; 1.2113x over previous
#include <cuda_runtime.h>
#include <cuda_bf16.h>
#include <cstdint>

#define DD 128
#define NMAX 100000
#define EMAX 1600000

// ---------------- static scratch (no allocations allowed) ----------------
__device__ int   g_cnt[NMAX];
__device__ int   g_rowptr[NMAX + 1];
__device__ int   g_col[EMAX];
__device__ __align__(16) float g_dinv[NMAX];
__device__ int   g_blocksums[256];
__device__ __align__(16) float g_B1[(size_t)NMAX * DD];
__device__ __align__(16) float g_B2[(size_t)NMAX * DD];
__device__ __align__(16) float g_B3[(size_t)NMAX * DD];
__device__ __align__(16) float g_B4[(size_t)NMAX * DD];
__device__ __align__(16) float g_M[DD * DD];
__device__ __align__(16) float g_bfin[DD];
__device__ __align__(16) float g_bsum[DD];
// bf16 weight images [matrix][hi/lo], layout [n][k] (k contiguous) for ldmatrix .col B
__device__ __align__(16) unsigned short g_wimg[5][2][16384];

enum Buf { B1 = 1, B2 = 2, B3 = 3, B4 = 4, BOUT = 6 };

__device__ __forceinline__ float* bufp(int sel, float* out) {
    switch (sel) {
        case B1: return g_B1;
        case B2: return g_B2;
        case B3: return g_B3;
        case B4: return g_B4;
        default: return out;
    }
}

// ---------------- warp-mma helpers (sm_80-era; legal on compute_100) ----------------
__device__ __forceinline__ uint32_t smem_u32(const void* p) {
    uint32_t a;
    asm("{ .reg .u64 t; cvta.to.shared.u64 t, %1; cvt.u32.u64 %0, t; }" : "=r"(a) : "l"(p));
    return a;
}
__device__ __forceinline__ void ldsm4(uint32_t* r, uint32_t addr) {
    asm volatile("ldmatrix.sync.aligned.m8n8.x4.shared.b16 {%0,%1,%2,%3}, [%4];"
                 : "=r"(r[0]), "=r"(r[1]), "=r"(r[2]), "=r"(r[3]) : "r"(addr));
}
__device__ __forceinline__ void mma_bf16(float* c, const uint32_t* a, const uint32_t* b) {
    asm volatile("mma.sync.aligned.m16n8k16.row.col.f32.bf16.bf16.f32 "
                 "{%0,%1,%2,%3}, {%4,%5,%6,%7}, {%8,%9}, {%0,%1,%2,%3};"
                 : "+f"(c[0]), "+f"(c[1]), "+f"(c[2]), "+f"(c[3])
                 : "r"(a[0]), "r"(a[1]), "r"(a[2]), "r"(a[3]), "r"(b[0]), "r"(b[1]));
}

// ---------------- CSR build ----------------
__global__ void k_zero_cnt(int n) {
    int i = blockIdx.x * blockDim.x + threadIdx.x;
    if (i < n) g_cnt[i] = 0;
}
__global__ void k_hist(const int* __restrict__ ei, int E, int n) {
    int e = blockIdx.x * blockDim.x + threadIdx.x;
    if (e < E) {
        int d = ei[E + e];
        if (d >= 0 && d < n) atomicAdd(&g_cnt[d], 1);
    }
}
__global__ void k_scan1(int n) {
    __shared__ int s[1024];
    int i = blockIdx.x * 1024 + threadIdx.x;
    int v = (i < n) ? g_cnt[i] : 0;
    s[threadIdx.x] = v;
    __syncthreads();
    for (int off = 1; off < 1024; off <<= 1) {
        int t = (threadIdx.x >= off) ? s[threadIdx.x - off] : 0;
        __syncthreads();
        s[threadIdx.x] += t;
        __syncthreads();
    }
    if (i < n) g_rowptr[i] = s[threadIdx.x] - v;
    if (threadIdx.x == 1023) g_blocksums[blockIdx.x] = s[1023];
}
__global__ void k_scan2(int nb) {
    __shared__ int s[256];
    int t = threadIdx.x;
    int v = (t < nb) ? g_blocksums[t] : 0;
    s[t] = v;
    __syncthreads();
    for (int off = 1; off < 256; off <<= 1) {
        int u = (t >= off) ? s[t - off] : 0;
        __syncthreads();
        s[t] += u;
        __syncthreads();
    }
    if (t < nb) g_blocksums[t] = s[t] - v;   // exclusive
}
__global__ void k_scan3(int n, int E) {
    int i = blockIdx.x * blockDim.x + threadIdx.x;
    if (i < n) {
        g_rowptr[i] += g_blocksums[i >> 10];
        g_dinv[i] = rsqrtf((float)g_cnt[i] + 1.0f);
        g_cnt[i] = 0;
    }
    if (i == 0) g_rowptr[n] = E;
}
__global__ void k_fill(const int* __restrict__ ei, int E, int n) {
    int e = blockIdx.x * blockDim.x + threadIdx.x;
    if (e < E) {
        int s = ei[e];
        int d = ei[E + e];
        if (s >= 0 && s < n && d >= 0 && d < n) {
            int pos = g_rowptr[d] + atomicAdd(&g_cnt[d], 1);
            g_col[pos] = s;
        }
    }
}

// ---------------- head fusion precompute ----------------
__global__ void k_mfuse(const float* __restrict__ lin_w, const float* __restrict__ lin_b,
                        const float* __restrict__ fc_w, const float* __restrict__ fc_b,
                        const float* __restrict__ gcn_b2, const float* __restrict__ gin_b2) {
    int c = threadIdx.x;
    if (blockIdx.x < DD) {
        int r = blockIdx.x;
        float a = 0.f;
        #pragma unroll 8
        for (int k = 0; k < DD; k++) a += lin_w[r * DD + k] * fc_w[k * DD + c];
        g_M[r * DD + c] = a;
    } else if (blockIdx.x == DD) {
        float a = 0.f;
        #pragma unroll 8
        for (int k = 0; k < DD; k++) a += lin_b[k] * fc_w[k * DD + c];
        g_bfin[c] = 2.f * a + fc_b[c];
    } else {
        g_bsum[c] = gcn_b2[c] + gin_b2[c];
    }
}

// ---------------- weight prep: W[k][n] fp32 -> bf16 hi/lo in [n][k] layout ----------------
__global__ void k_wprep(const float* __restrict__ w0, const float* __restrict__ w1,
                        const float* __restrict__ w2, const float* __restrict__ w3) {
    int mat = blockIdx.y;
    int i = blockIdx.x * 256 + threadIdx.x;
    if (i >= 16384) return;
    int k = i >> 7, nn = i & 127;
    const float* W = (mat == 0) ? w0 : (mat == 1) ? w1 : (mat == 2) ? w2 : (mat == 3) ? w3 : g_M;
    float x = W[k * 128 + nn];
    __nv_bfloat16 hi = __float2bfloat16(x);
    __nv_bfloat16 lo = __float2bfloat16(x - __bfloat162float(hi));
    g_wimg[mat][0][nn * 128 + k] = __bfloat16_as_ushort(hi);
    g_wimg[mat][1][nn * 128 + k] = __bfloat16_as_ushort(lo);
}

// ---------------- aggregation: warp per node ----------------
__global__ void k_agg1(const float* __restrict__ X, int n) {
    int w = (blockIdx.x * blockDim.x + threadIdx.x) >> 5;
    if (w >= n) return;
    int lane = threadIdx.x & 31;
    const float4* Xv = (const float4*)X;
    int e = g_rowptr[w], end = g_rowptr[w + 1];
    float4 aw = make_float4(0, 0, 0, 0), au = make_float4(0, 0, 0, 0);
    for (; e < end; e++) {
        int j = g_col[e];
        float dj = g_dinv[j];
        float4 v = Xv[(size_t)j * 32 + lane];
        aw.x += dj * v.x; aw.y += dj * v.y; aw.z += dj * v.z; aw.w += dj * v.w;
        au.x += v.x;      au.y += v.y;      au.z += v.z;      au.w += v.w;
    }
    float di = g_dinv[w], dii = di * di;
    float4 xi = Xv[(size_t)w * 32 + lane];
    float4 ow, ou;
    ow.x = di * aw.x + dii * xi.x; ow.y = di * aw.y + dii * xi.y;
    ow.z = di * aw.z + dii * xi.z; ow.w = di * aw.w + dii * xi.w;
    ou.x = au.x + xi.x; ou.y = au.y + xi.y; ou.z = au.z + xi.z; ou.w = au.w + xi.w;
    ((float4*)g_B1)[(size_t)w * 32 + lane] = ow;
    ((float4*)g_B2)[(size_t)w * 32 + lane] = ou;
}
__global__ void k_agg2(int n) {
    int w = (blockIdx.x * blockDim.x + threadIdx.x) >> 5;
    if (w >= n) return;
    int lane = threadIdx.x & 31;
    const float4* Hv = (const float4*)g_B3;
    const float4* Gv = (const float4*)g_B4;
    int e = g_rowptr[w], end = g_rowptr[w + 1];
    float4 aw = make_float4(0, 0, 0, 0), au = make_float4(0, 0, 0, 0);
    for (; e < end; e++) {
        int j = g_col[e];
        float dj = g_dinv[j];
        float4 hv = Hv[(size_t)j * 32 + lane];
        float4 gv = Gv[(size_t)j * 32 + lane];
        aw.x += dj * hv.x; aw.y += dj * hv.y; aw.z += dj * hv.z; aw.w += dj * hv.w;
        au.x += gv.x;      au.y += gv.y;      au.z += gv.z;      au.w += gv.w;
    }
    float di = g_dinv[w], dii = di * di;
    float4 hi = Hv[(size_t)w * 32 + lane];
    float4 gi = Gv[(size_t)w * 32 + lane];
    float4 ow, ou;
    ow.x = di * aw.x + dii * hi.x; ow.y = di * aw.y + dii * hi.y;
    ow.z = di * aw.z + dii * hi.z; ow.w = di * aw.w + dii * hi.w;
    ou.x = au.x + gi.x; ou.y = au.y + gi.y; ou.z = au.z + gi.z; ou.w = au.w + gi.w;
    ((float4*)g_B1)[(size_t)w * 32 + lane] = ow;
    ((float4*)g_B2)[(size_t)w * 32 + lane] = ou;
}

// ---------------- warp-mma bf16 split GEMM ----------------
// C[tile 128, 128] = sum_pass A_pass @ W_pass (+bias, opt relu), fp32 in/out.
// Split: Ah*Wh + Al*Wh + Ah*Wl. K in 4 chunks of 32; per chunk 3 terms x 2 k16-steps.
// 8 warps: 4(m) x 2(n); warp tile 32x64 = 2x8 m16n8k16 tiles.
#define SAST 40   // smem row stride in bf16 elems (80B: 16B-aligned, ldmatrix conflict-free)
template <bool RELU, int SELA1, int SELA2, int SELC, int W1IDX, int W2IDX, int BIAS_SEL>
__global__ void __launch_bounds__(256) k_tgemm(const float* __restrict__ bias_param,
                                               float* __restrict__ outp, int n) {
    __shared__ __align__(16) unsigned short sAh[128 * SAST], sAl[128 * SAST];
    __shared__ __align__(16) unsigned short sWh[128 * SAST], sWl[128 * SAST];

    int tid = threadIdx.x, lane = tid & 31, wid = tid >> 5;
    int wm = wid & 3, wn = wid >> 2;
    int row0 = blockIdx.x * 128;

    uint32_t sAh_b = smem_u32(sAh), sAl_b = smem_u32(sAl);
    uint32_t sWh_b = smem_u32(sWh), sWl_b = smem_u32(sWl);

    float acc[2][8][4];
    #pragma unroll
    for (int i = 0; i < 2; i++)
        #pragma unroll
        for (int j = 0; j < 8; j++)
            #pragma unroll
            for (int q = 0; q < 4; q++) acc[i][j][q] = 0.f;

    const int npass = (SELA2 != 0) ? 2 : 1;
    for (int pass = 0; pass < npass; pass++) {
        const float4* Av = (const float4*)bufp(pass ? SELA2 : SELA1, outp);
        const int widx = pass ? W2IDX : W1IDX;
        const unsigned short* wh = g_wimg[widx][0];
        const unsigned short* wl = g_wimg[widx][1];

        for (int kc = 0; kc < 4; kc++) {
            __syncthreads();   // previous chunk's ldmatrix done before overwrite

            // stage A chunk: 128 rows x 32 k fp32 -> hi/lo bf16
            #pragma unroll
            for (int f = tid; f < 1024; f += 256) {
                int r = f >> 3, q = f & 7;
                int gr = row0 + r;
                float4 v = (gr < n) ? Av[(size_t)gr * 32 + kc * 8 + q]
                                    : make_float4(0, 0, 0, 0);
                float xs[4] = {v.x, v.y, v.z, v.w};
                unsigned short h[4], l[4];
                #pragma unroll
                for (int j = 0; j < 4; j++) {
                    __nv_bfloat16 bh = __float2bfloat16(xs[j]);
                    __nv_bfloat16 bl = __float2bfloat16(xs[j] - __bfloat162float(bh));
                    h[j] = __bfloat16_as_ushort(bh);
                    l[j] = __bfloat16_as_ushort(bl);
                }
                uint2 ph, pl;
                ph.x = (uint32_t)h[0] | ((uint32_t)h[1] << 16);
                ph.y = (uint32_t)h[2] | ((uint32_t)h[3] << 16);
                pl.x = (uint32_t)l[0] | ((uint32_t)l[1] << 16);
                pl.y = (uint32_t)l[2] | ((uint32_t)l[3] << 16);
                *(uint2*)&sAh[r * SAST + q * 4] = ph;
                *(uint2*)&sAl[r * SAST + q * 4] = pl;
            }
            // stage W chunk: 128 n-rows x 32 k bf16 (hi and lo), straight copy
            #pragma unroll
            for (int f = tid; f < 512; f += 256) {
                int r = f >> 2, q = f & 3;
                const uint4* srch = (const uint4*)(wh + r * 128 + kc * 32);
                const uint4* srcl = (const uint4*)(wl + r * 128 + kc * 32);
                *(uint4*)&sWh[r * SAST + q * 8] = srch[q];
                *(uint4*)&sWl[r * SAST + q * 8] = srcl[q];
            }
            __syncthreads();

            #pragma unroll
            for (int term = 0; term < 3; term++) {
                uint32_t aBase = (term == 1) ? sAl_b : sAh_b;
                uint32_t wBase = (term == 2) ? sWl_b : sWh_b;
                #pragma unroll
                for (int ks = 0; ks < 2; ks++) {
                    int k0 = ks * 16;
                    uint32_t a[2][4], b[8][2];
                    #pragma unroll
                    for (int mi = 0; mi < 2; mi++) {
                        int m0 = wm * 32 + mi * 16;
                        uint32_t addr = aBase +
                            (((m0 + (lane & 15)) * SAST) + k0 + (lane >> 4) * 8) * 2;
                        ldsm4(a[mi], addr);
                    }
                    #pragma unroll
                    for (int q = 0; q < 4; q++) {
                        int nb = wn * 64 + q * 16;
                        int rown = nb + ((lane >> 4) << 3) + (lane & 7);
                        int kk = k0 + (((lane >> 3) & 1) << 3);
                        uint32_t addr = wBase + ((rown * SAST) + kk) * 2;
                        uint32_t r4[4];
                        ldsm4(r4, addr);
                        b[q * 2 + 0][0] = r4[0]; b[q * 2 + 0][1] = r4[1];
                        b[q * 2 + 1][0] = r4[2]; b[q * 2 + 1][1] = r4[3];
                    }
                    #pragma unroll
                    for (int mi = 0; mi < 2; mi++)
                        #pragma unroll
                        for (int nj = 0; nj < 8; nj++)
                            mma_bf16(acc[mi][nj], a[mi], b[nj]);
                }
            }
        }
    }

    // epilogue
    const float* bias_p = (BIAS_SEL == 1) ? g_bsum : (BIAS_SEL == 2) ? g_bfin : bias_param;
    float* C = bufp(SELC, outp);
    int rbase = row0 + wm * 32 + (lane >> 2);
    int cbase = wn * 64 + (lane & 3) * 2;
    #pragma unroll
    for (int mi = 0; mi < 2; mi++) {
        #pragma unroll
        for (int half = 0; half < 2; half++) {
            int gr = rbase + mi * 16 + half * 8;
            if (gr >= n) continue;
            #pragma unroll
            for (int nj = 0; nj < 8; nj++) {
                int col = cbase + nj * 8;
                float v0 = acc[mi][nj][half * 2 + 0] + bias_p[col];
                float v1 = acc[mi][nj][half * 2 + 1] + bias_p[col + 1];
                if (RELU) { v0 = fmaxf(v0, 0.f); v1 = fmaxf(v1, 0.f); }
                *(float2*)&C[(size_t)gr * 128 + col] = make_float2(v0, v1);
            }
        }
    }
}

// ---------------- launch ----------------
extern "C" void kernel_launch(void* const* d_in, const int* in_sizes, int n_in,
                              void* d_out, int out_size) {
    const float* X      = (const float*)d_in[0];
    const int*   ei     = (const int*)d_in[1];
    const float* gcn_w1 = (const float*)d_in[2];
    const float* gcn_b1 = (const float*)d_in[3];
    const float* gcn_w2 = (const float*)d_in[4];
    const float* gcn_b2 = (const float*)d_in[5];
    const float* gin_w1 = (const float*)d_in[6];
    const float* gin_b1 = (const float*)d_in[7];
    const float* gin_w2 = (const float*)d_in[8];
    const float* gin_b2 = (const float*)d_in[9];
    const float* lin_w  = (const float*)d_in[10];
    const float* lin_b  = (const float*)d_in[11];
    const float* fc_w   = (const float*)d_in[12];
    const float* fc_b   = (const float*)d_in[13];
    float*       out    = (float*)d_out;

    int N = in_sizes[0] / DD;
    int E = in_sizes[1] / 2;

    int nb = (N + 1023) / 1024;
    int gN = (N + 255) / 256;
    int gE = (E + 255) / 256;
    int gW = (N + 7) / 8;
    int gG = (N + 127) / 128;

    // CSR build
    k_zero_cnt<<<gN, 256>>>(N);
    k_hist<<<gE, 256>>>(ei, E, N);
    k_scan1<<<nb, 1024>>>(N);
    k_scan2<<<1, 256>>>(nb);
    k_scan3<<<gN, 256>>>(N, E);
    k_fill<<<gE, 256>>>(ei, E, N);

    // head fusion + weight images (mfuse before wprep: g_M feeds image 4)
    k_mfuse<<<DD + 2, DD>>>(lin_w, lin_b, fc_w, fc_b, gcn_b2, gin_b2);
    k_wprep<<<dim3(64, 5), 256>>>(gcn_w1, gin_w1, gcn_w2, gin_w2);

    // layer 1: aggregate raw X once for both branches
    k_agg1<<<gW, 256>>>(X, N);
    // h = relu(aggW @ gcn_w1 + gcn_b1)   B1 -> B3  (wimg 0)
    k_tgemm<true,  B1, 0,  B3,   0, 0, 0><<<gG, 256>>>(gcn_b1, out, N);
    // g = aggU @ gin_w1 + gin_b1         B2 -> B4  (wimg 1)
    k_tgemm<false, B2, 0,  B4,   1, 0, 0><<<gG, 256>>>(gin_b1, out, N);

    // layer 2 aggregation (B3,B4 -> B1,B2)
    k_agg2<<<gW, 256>>>(N);
    // S = aggW2 @ gcn_w2 + aggU2 @ gin_w2 + (gcn_b2+gin_b2)  -> B3 (wimg 2,3; bias g_bsum)
    k_tgemm<false, B1, B2, B3,   2, 3, 1><<<gG, 256>>>(gcn_b2, out, N);
    // out = S @ (lin_w@fc_w) + g_bfin    (wimg 4)
    k_tgemm<false, B3, 0,  BOUT, 4, 0, 2><<<gG, 256>>>(fc_b, out, N);
}

// round 8
// speedup vs baseline: 1.2931x; 1.0675x over previous
#include <cuda_runtime.h>
#include <cuda_bf16.h>
#include <cstdint>

#define DD 128
#define NMAX 100000
#define EMAX 1600000

// ---------------- static scratch ----------------
__device__ int   g_cnt[NMAX];
__device__ int   g_rowptr[NMAX + 1];
__device__ int   g_col[EMAX];
__device__ __align__(16) float g_dinv[NMAX];
__device__ int   g_blocksums[256];
__device__ __align__(16) float g_M[DD * DD];
__device__ __align__(16) float g_bfin[DD];
__device__ __align__(16) float g_bsum[DD];
// bf16 weight images [matrix][hi/lo], layout [n][k] (k contiguous)
__device__ __align__(16) unsigned short g_wimg[5][2][16384];
// split intermediate panels: value = hi + lo (bf16 each), layout [node][128]
// 0: aggW (GCN gemm in)   1: aggU (GIN gemm in)   2: h / S   3: g
__device__ __align__(16) unsigned short g_Ph[4][(size_t)NMAX * DD];
__device__ __align__(16) unsigned short g_Pl[4][(size_t)NMAX * DD];

// ---------------- PTX helpers ----------------
__device__ __forceinline__ uint32_t smem_u32(const void* p) {
    uint32_t a;
    asm("{ .reg .u64 t; cvta.to.shared.u64 t, %1; cvt.u32.u64 %0, t; }" : "=r"(a) : "l"(p));
    return a;
}
__device__ __forceinline__ void ldsm4(uint32_t* r, uint32_t addr) {
    asm volatile("ldmatrix.sync.aligned.m8n8.x4.shared.b16 {%0,%1,%2,%3}, [%4];"
                 : "=r"(r[0]), "=r"(r[1]), "=r"(r[2]), "=r"(r[3]) : "r"(addr));
}
__device__ __forceinline__ void mma_bf16(float* c, const uint32_t* a, const uint32_t* b) {
    asm volatile("mma.sync.aligned.m16n8k16.row.col.f32.bf16.bf16.f32 "
                 "{%0,%1,%2,%3}, {%4,%5,%6,%7}, {%8,%9}, {%0,%1,%2,%3};"
                 : "+f"(c[0]), "+f"(c[1]), "+f"(c[2]), "+f"(c[3])
                 : "r"(a[0]), "r"(a[1]), "r"(a[2]), "r"(a[3]), "r"(b[0]), "r"(b[1]));
}
__device__ __forceinline__ void cpasync16(uint32_t dst, const void* src, int szbytes) {
    asm volatile("cp.async.cg.shared.global [%0], [%1], 16, %2;"
                 :: "r"(dst), "l"(src), "r"(szbytes) : "memory");
}
__device__ __forceinline__ void cp_commit() { asm volatile("cp.async.commit_group;" ::: "memory"); }
template <int N> __device__ __forceinline__ void cp_wait() {
    asm volatile("cp.async.wait_group %0;" :: "n"(N) : "memory");
}
// conflict-free chunk16 tile: row r (0..127) of 16 bf16 = 2x16B octets, stride 32B
__device__ __forceinline__ uint32_t swz(int r, int p) {
    return (uint32_t)(r * 32 + ((p ^ (r & 1) ^ ((r >> 2) & 1)) << 4));
}
// split/merge helpers
__device__ __forceinline__ void split4(float4 v, uint2& h, uint2& l) {
    __nv_bfloat16 h0 = __float2bfloat16(v.x), h1 = __float2bfloat16(v.y);
    __nv_bfloat16 h2 = __float2bfloat16(v.z), h3 = __float2bfloat16(v.w);
    __nv_bfloat16 l0 = __float2bfloat16(v.x - __bfloat162float(h0));
    __nv_bfloat16 l1 = __float2bfloat16(v.y - __bfloat162float(h1));
    __nv_bfloat16 l2 = __float2bfloat16(v.z - __bfloat162float(h2));
    __nv_bfloat16 l3 = __float2bfloat16(v.w - __bfloat162float(h3));
    h.x = (uint32_t)__bfloat16_as_ushort(h0) | ((uint32_t)__bfloat16_as_ushort(h1) << 16);
    h.y = (uint32_t)__bfloat16_as_ushort(h2) | ((uint32_t)__bfloat16_as_ushort(h3) << 16);
    l.x = (uint32_t)__bfloat16_as_ushort(l0) | ((uint32_t)__bfloat16_as_ushort(l1) << 16);
    l.y = (uint32_t)__bfloat16_as_ushort(l2) | ((uint32_t)__bfloat16_as_ushort(l3) << 16);
}
__device__ __forceinline__ float4 load_split4(const unsigned short* ph, const unsigned short* pl,
                                              size_t idx) {
    uint2 h = *(const uint2*)(ph + idx);
    uint2 l = *(const uint2*)(pl + idx);
    float4 r;
    r.x = __uint_as_float(h.x << 16) + __uint_as_float(l.x << 16);
    r.y = __uint_as_float(h.x & 0xFFFF0000u) + __uint_as_float(l.x & 0xFFFF0000u);
    r.z = __uint_as_float(h.y << 16) + __uint_as_float(l.y << 16);
    r.w = __uint_as_float(h.y & 0xFFFF0000u) + __uint_as_float(l.y & 0xFFFF0000u);
    return r;
}

// ---------------- CSR build ----------------
__global__ void k_zero_cnt(int n) {
    int i = blockIdx.x * blockDim.x + threadIdx.x;
    if (i < n) g_cnt[i] = 0;
}
__global__ void k_hist(const int* __restrict__ ei, int E, int n) {
    int e = blockIdx.x * blockDim.x + threadIdx.x;
    if (e < E) {
        int d = ei[E + e];
        if (d >= 0 && d < n) atomicAdd(&g_cnt[d], 1);
    }
}
__global__ void k_scan1(int n) {
    __shared__ int s[1024];
    int i = blockIdx.x * 1024 + threadIdx.x;
    int v = (i < n) ? g_cnt[i] : 0;
    s[threadIdx.x] = v;
    __syncthreads();
    for (int off = 1; off < 1024; off <<= 1) {
        int t = (threadIdx.x >= off) ? s[threadIdx.x - off] : 0;
        __syncthreads();
        s[threadIdx.x] += t;
        __syncthreads();
    }
    if (i < n) g_rowptr[i] = s[threadIdx.x] - v;
    if (threadIdx.x == 1023) g_blocksums[blockIdx.x] = s[1023];
}
__global__ void k_scan2(int nb) {
    __shared__ int s[256];
    int t = threadIdx.x;
    int v = (t < nb) ? g_blocksums[t] : 0;
    s[t] = v;
    __syncthreads();
    for (int off = 1; off < 256; off <<= 1) {
        int u = (t >= off) ? s[t - off] : 0;
        __syncthreads();
        s[t] += u;
        __syncthreads();
    }
    if (t < nb) g_blocksums[t] = s[t] - v;
}
__global__ void k_scan3(int n, int E) {
    int i = blockIdx.x * blockDim.x + threadIdx.x;
    if (i < n) {
        g_rowptr[i] += g_blocksums[i >> 10];
        g_dinv[i] = rsqrtf((float)g_cnt[i] + 1.0f);
        g_cnt[i] = 0;
    }
    if (i == 0) g_rowptr[n] = E;
}
__global__ void k_fill(const int* __restrict__ ei, int E, int n) {
    int e = blockIdx.x * blockDim.x + threadIdx.x;
    if (e < E) {
        int s = ei[e];
        int d = ei[E + e];
        if (s >= 0 && s < n && d >= 0 && d < n) {
            int pos = g_rowptr[d] + atomicAdd(&g_cnt[d], 1);
            g_col[pos] = s;
        }
    }
}

// ---------------- head fusion precompute ----------------
__global__ void k_mfuse(const float* __restrict__ lin_w, const float* __restrict__ lin_b,
                        const float* __restrict__ fc_w, const float* __restrict__ fc_b,
                        const float* __restrict__ gcn_b2, const float* __restrict__ gin_b2) {
    int c = threadIdx.x;
    if (blockIdx.x < DD) {
        int r = blockIdx.x;
        float a = 0.f;
        #pragma unroll 8
        for (int k = 0; k < DD; k++) a += lin_w[r * DD + k] * fc_w[k * DD + c];
        g_M[r * DD + c] = a;
    } else if (blockIdx.x == DD) {
        float a = 0.f;
        #pragma unroll 8
        for (int k = 0; k < DD; k++) a += lin_b[k] * fc_w[k * DD + c];
        g_bfin[c] = 2.f * a + fc_b[c];
    } else {
        g_bsum[c] = gcn_b2[c] + gin_b2[c];
    }
}

// ---------------- weight prep: W[k][n] fp32 -> bf16 hi/lo in [n][k] ----------------
__global__ void k_wprep(const float* __restrict__ w0, const float* __restrict__ w1,
                        const float* __restrict__ w2, const float* __restrict__ w3) {
    int mat = blockIdx.y;
    int i = blockIdx.x * 256 + threadIdx.x;
    if (i >= 16384) return;
    int k = i >> 7, nn = i & 127;
    const float* W = (mat == 0) ? w0 : (mat == 1) ? w1 : (mat == 2) ? w2 : (mat == 3) ? w3 : g_M;
    float x = W[k * 128 + nn];
    __nv_bfloat16 hi = __float2bfloat16(x);
    __nv_bfloat16 lo = __float2bfloat16(x - __bfloat162float(hi));
    g_wimg[mat][0][nn * 128 + k] = __bfloat16_as_ushort(hi);
    g_wimg[mat][1][nn * 128 + k] = __bfloat16_as_ushort(lo);
}

// ---------------- aggregation (warp per node, batched edges, split IO) ----------------
__global__ void k_agg1(const float* __restrict__ X, int n) {
    int w = (blockIdx.x * blockDim.x + threadIdx.x) >> 5;
    if (w >= n) return;
    int lane = threadIdx.x & 31;
    const float4* Xv = (const float4*)X;
    int e = g_rowptr[w], end = g_rowptr[w + 1];
    float4 aw = make_float4(0, 0, 0, 0), au = make_float4(0, 0, 0, 0);
    for (; e + 4 <= end; e += 4) {
        int j0 = g_col[e], j1 = g_col[e + 1], j2 = g_col[e + 2], j3 = g_col[e + 3];
        float d0 = g_dinv[j0], d1 = g_dinv[j1], d2 = g_dinv[j2], d3 = g_dinv[j3];
        float4 v0 = Xv[(size_t)j0 * 32 + lane];
        float4 v1 = Xv[(size_t)j1 * 32 + lane];
        float4 v2 = Xv[(size_t)j2 * 32 + lane];
        float4 v3 = Xv[(size_t)j3 * 32 + lane];
        aw.x += d0 * v0.x + d1 * v1.x + d2 * v2.x + d3 * v3.x;
        aw.y += d0 * v0.y + d1 * v1.y + d2 * v2.y + d3 * v3.y;
        aw.z += d0 * v0.z + d1 * v1.z + d2 * v2.z + d3 * v3.z;
        aw.w += d0 * v0.w + d1 * v1.w + d2 * v2.w + d3 * v3.w;
        au.x += v0.x + v1.x + v2.x + v3.x;
        au.y += v0.y + v1.y + v2.y + v3.y;
        au.z += v0.z + v1.z + v2.z + v3.z;
        au.w += v0.w + v1.w + v2.w + v3.w;
    }
    for (; e < end; e++) {
        int j = g_col[e];
        float dj = g_dinv[j];
        float4 v = Xv[(size_t)j * 32 + lane];
        aw.x += dj * v.x; aw.y += dj * v.y; aw.z += dj * v.z; aw.w += dj * v.w;
        au.x += v.x;      au.y += v.y;      au.z += v.z;      au.w += v.w;
    }
    float di = g_dinv[w], dii = di * di;
    float4 xi = Xv[(size_t)w * 32 + lane];
    float4 ow, ou;
    ow.x = di * aw.x + dii * xi.x; ow.y = di * aw.y + dii * xi.y;
    ow.z = di * aw.z + dii * xi.z; ow.w = di * aw.w + dii * xi.w;
    ou.x = au.x + xi.x; ou.y = au.y + xi.y; ou.z = au.z + xi.z; ou.w = au.w + xi.w;
    size_t idx = (size_t)w * 128 + lane * 4;
    uint2 h, l;
    split4(ow, h, l);
    *(uint2*)&g_Ph[0][idx] = h;  *(uint2*)&g_Pl[0][idx] = l;
    split4(ou, h, l);
    *(uint2*)&g_Ph[1][idx] = h;  *(uint2*)&g_Pl[1][idx] = l;
}
__global__ void k_agg2(int n) {
    int w = (blockIdx.x * blockDim.x + threadIdx.x) >> 5;
    if (w >= n) return;
    int lane = threadIdx.x & 31;
    int e = g_rowptr[w], end = g_rowptr[w + 1];
    float4 aw = make_float4(0, 0, 0, 0), au = make_float4(0, 0, 0, 0);
    for (; e + 2 <= end; e += 2) {
        int j0 = g_col[e], j1 = g_col[e + 1];
        float d0 = g_dinv[j0], d1 = g_dinv[j1];
        size_t i0 = (size_t)j0 * 128 + lane * 4, i1 = (size_t)j1 * 128 + lane * 4;
        float4 h0 = load_split4(g_Ph[2], g_Pl[2], i0);
        float4 h1 = load_split4(g_Ph[2], g_Pl[2], i1);
        float4 g0 = load_split4(g_Ph[3], g_Pl[3], i0);
        float4 g1 = load_split4(g_Ph[3], g_Pl[3], i1);
        aw.x += d0 * h0.x + d1 * h1.x; aw.y += d0 * h0.y + d1 * h1.y;
        aw.z += d0 * h0.z + d1 * h1.z; aw.w += d0 * h0.w + d1 * h1.w;
        au.x += g0.x + g1.x; au.y += g0.y + g1.y;
        au.z += g0.z + g1.z; au.w += g0.w + g1.w;
    }
    for (; e < end; e++) {
        int j = g_col[e];
        float dj = g_dinv[j];
        size_t i0 = (size_t)j * 128 + lane * 4;
        float4 hv = load_split4(g_Ph[2], g_Pl[2], i0);
        float4 gv = load_split4(g_Ph[3], g_Pl[3], i0);
        aw.x += dj * hv.x; aw.y += dj * hv.y; aw.z += dj * hv.z; aw.w += dj * hv.w;
        au.x += gv.x;      au.y += gv.y;      au.z += gv.z;      au.w += gv.w;
    }
    float di = g_dinv[w], dii = di * di;
    size_t iw = (size_t)w * 128 + lane * 4;
    float4 hi = load_split4(g_Ph[2], g_Pl[2], iw);
    float4 gi = load_split4(g_Ph[3], g_Pl[3], iw);
    float4 ow, ou;
    ow.x = di * aw.x + dii * hi.x; ow.y = di * aw.y + dii * hi.y;
    ow.z = di * aw.z + dii * hi.z; ow.w = di * aw.w + dii * hi.w;
    ou.x = au.x + gi.x; ou.y = au.y + gi.y; ou.z = au.z + gi.z; ou.w = au.w + gi.w;
    uint2 h, l;
    split4(ow, h, l);
    *(uint2*)&g_Ph[0][iw] = h;  *(uint2*)&g_Pl[0][iw] = l;
    split4(ou, h, l);
    *(uint2*)&g_Ph[1][iw] = h;  *(uint2*)&g_Pl[1][iw] = l;
}

// ---------------- pipelined warp-mma split GEMM ----------------
// C_tile[128,128] = sum_pass A_pass @ W_pass; split terms Ah*Wh + Al*Wh + Ah*Wl.
// K chunks of 16; 2-stage cp.async double buffer; 8 warps = 4(m) x 2(n), warp 32x64.
template <bool RELU, bool DUAL, int INA1, int INA2, int OUTI, int W1I, int W2I,
          int BSEL, bool OUTF32>
__device__ __forceinline__ void tgemm_body(int bx, const float* bias_param,
                                           float* outp, int n, uint32_t sbase) {
    int tid = threadIdx.x, lane = tid & 31, wid = tid >> 5;
    int wm = wid & 3, wn = wid >> 2;
    int row0 = bx * 128;

    float acc[2][8][4];
    #pragma unroll
    for (int i = 0; i < 2; i++)
        #pragma unroll
        for (int j = 0; j < 8; j++)
            #pragma unroll
            for (int q = 0; q < 4; q++) acc[i][j][q] = 0.f;

    const int T = DUAL ? 16 : 8;
    int sr = tid >> 1, sp = tid & 1;               // staging piece owned by this thread
    uint32_t soff = swz(sr, sp);
    int sgr = row0 + sr;
    bool svalid = sgr < n;
    size_t s_asrc = (size_t)(svalid ? sgr : 0) * 128 + sp * 8;
    size_t s_wsrc = (size_t)sr * 128 + sp * 8;

    auto do_stage = [&](int c) {
        int pass = DUAL ? (c >> 3) : 0;
        int kc = c & 7, s = c & 1;
        const unsigned short* Ah = g_Ph[pass ? INA2 : INA1];
        const unsigned short* Al = g_Pl[pass ? INA2 : INA1];
        int wi = pass ? W2I : W1I;
        uint32_t b = sbase + s * 16384;
        size_t ka = s_asrc + kc * 16, kw = s_wsrc + kc * 16;
        cpasync16(b + soff,         Ah + ka, svalid ? 16 : 0);
        cpasync16(b + 4096 + soff,  Al + ka, svalid ? 16 : 0);
        cpasync16(b + 8192 + soff,  g_wimg[wi][0] + kw, 16);
        cpasync16(b + 12288 + soff, g_wimg[wi][1] + kw, 16);
    };

    do_stage(0);
    cp_commit();

    for (int c = 0; c < T; c++) {
        if (c + 1 < T) {
            do_stage(c + 1);
            cp_commit();
            cp_wait<1>();
        } else {
            cp_wait<0>();
        }
        __syncthreads();

        uint32_t b0 = sbase + (c & 1) * 16384;
        #pragma unroll
        for (int term = 0; term < 3; term++) {
            uint32_t ab = b0 + ((term == 1) ? 4096 : 0);
            uint32_t wb = b0 + 8192 + ((term == 2) ? 4096 : 0);
            uint32_t a[2][4], bf[8][2];
            #pragma unroll
            for (int mi = 0; mi < 2; mi++) {
                int row = wm * 32 + mi * 16 + (lane & 15);
                ldsm4(a[mi], ab + swz(row, lane >> 4));
            }
            #pragma unroll
            for (int q = 0; q < 4; q++) {
                int rown = wn * 64 + q * 16 + ((lane >> 4) << 3) + (lane & 7);
                uint32_t r4[4];
                ldsm4(r4, wb + swz(rown, (lane >> 3) & 1));
                bf[q * 2 + 0][0] = r4[0]; bf[q * 2 + 0][1] = r4[1];
                bf[q * 2 + 1][0] = r4[2]; bf[q * 2 + 1][1] = r4[3];
            }
            #pragma unroll
            for (int mi = 0; mi < 2; mi++)
                #pragma unroll
                for (int nj = 0; nj < 8; nj++)
                    mma_bf16(acc[mi][nj], a[mi], bf[nj]);
        }
        __syncthreads();
    }

    // epilogue
    const float* bias_p = (BSEL == 1) ? g_bsum : (BSEL == 2) ? g_bfin : bias_param;
    int rbase = row0 + wm * 32 + (lane >> 2);
    int cbase = wn * 64 + (lane & 3) * 2;
    #pragma unroll
    for (int mi = 0; mi < 2; mi++) {
        #pragma unroll
        for (int half = 0; half < 2; half++) {
            int gr = rbase + mi * 16 + half * 8;
            if (gr >= n) continue;
            #pragma unroll
            for (int nj = 0; nj < 8; nj++) {
                int col = cbase + nj * 8;
                float v0 = acc[mi][nj][half * 2 + 0] + bias_p[col];
                float v1 = acc[mi][nj][half * 2 + 1] + bias_p[col + 1];
                if (RELU) { v0 = fmaxf(v0, 0.f); v1 = fmaxf(v1, 0.f); }
                if (OUTF32) {
                    *(float2*)&outp[(size_t)gr * 128 + col] = make_float2(v0, v1);
                } else {
                    __nv_bfloat16 h0 = __float2bfloat16(v0), h1 = __float2bfloat16(v1);
                    __nv_bfloat16 l0 = __float2bfloat16(v0 - __bfloat162float(h0));
                    __nv_bfloat16 l1 = __float2bfloat16(v1 - __bfloat162float(h1));
                    size_t o = (size_t)gr * 128 + col;
                    *(uint32_t*)&g_Ph[OUTI][o] =
                        (uint32_t)__bfloat16_as_ushort(h0) | ((uint32_t)__bfloat16_as_ushort(h1) << 16);
                    *(uint32_t*)&g_Pl[OUTI][o] =
                        (uint32_t)__bfloat16_as_ushort(l0) | ((uint32_t)__bfloat16_as_ushort(l1) << 16);
                }
            }
        }
    }
}

// layer-1 pair: first half of grid = GCN branch, second half = GIN branch
__global__ void __launch_bounds__(256, 2) k_tgemm_l1(const float* __restrict__ b1,
                                                     const float* __restrict__ b2,
                                                     float* __restrict__ outp, int n, int half) {
    __shared__ __align__(1024) unsigned char sbuf[2 * 4 * 4096];
    uint32_t sbase = smem_u32(sbuf);
    if ((int)blockIdx.x < half)
        tgemm_body<true,  false, 0, 0, 2, 0, 0, 0, false>(blockIdx.x, b1, outp, n, sbase);
    else
        tgemm_body<false, false, 1, 0, 3, 1, 0, 0, false>(blockIdx.x - half, b2, outp, n, sbase);
}
// layer-2 dual-accumulate GEMM:  S = aggW2@w2 + aggU2@w3 + bsum  -> P2 split
__global__ void __launch_bounds__(256, 2) k_tgemm_l2(float* __restrict__ outp, int n) {
    __shared__ __align__(1024) unsigned char sbuf[2 * 4 * 4096];
    tgemm_body<false, true, 0, 1, 2, 2, 3, 1, false>(blockIdx.x, outp, outp, n, smem_u32(sbuf));
}
// final head GEMM: out = S @ M + bfin  (fp32 out)
__global__ void __launch_bounds__(256, 2) k_tgemm_fin(float* __restrict__ outp, int n) {
    __shared__ __align__(1024) unsigned char sbuf[2 * 4 * 4096];
    tgemm_body<false, false, 2, 0, 0, 4, 0, 2, true>(blockIdx.x, outp, outp, n, smem_u32(sbuf));
}

// ---------------- launch ----------------
extern "C" void kernel_launch(void* const* d_in, const int* in_sizes, int n_in,
                              void* d_out, int out_size) {
    const float* X      = (const float*)d_in[0];
    const int*   ei     = (const int*)d_in[1];
    const float* gcn_w1 = (const float*)d_in[2];
    const float* gcn_b1 = (const float*)d_in[3];
    const float* gcn_w2 = (const float*)d_in[4];
    const float* gcn_b2 = (const float*)d_in[5];
    const float* gin_w1 = (const float*)d_in[6];
    const float* gin_b1 = (const float*)d_in[7];
    const float* gin_w2 = (const float*)d_in[8];
    const float* gin_b2 = (const float*)d_in[9];
    const float* lin_w  = (const float*)d_in[10];
    const float* lin_b  = (const float*)d_in[11];
    const float* fc_w   = (const float*)d_in[12];
    const float* fc_b   = (const float*)d_in[13];
    float*       out    = (float*)d_out;

    int N = in_sizes[0] / DD;
    int E = in_sizes[1] / 2;

    int nb = (N + 1023) / 1024;
    int gN = (N + 255) / 256;
    int gE = (E + 255) / 256;
    int gW = (N + 7) / 8;
    int gG = (N + 127) / 128;

    // CSR build
    k_zero_cnt<<<gN, 256>>>(N);
    k_hist<<<gE, 256>>>(ei, E, N);
    k_scan1<<<nb, 1024>>>(N);
    k_scan2<<<1, 256>>>(nb);
    k_scan3<<<gN, 256>>>(N, E);
    k_fill<<<gE, 256>>>(ei, E, N);

    // head fusion + weight images
    k_mfuse<<<DD + 2, DD>>>(lin_w, lin_b, fc_w, fc_b, gcn_b2, gin_b2);
    k_wprep<<<dim3(64, 5), 256>>>(gcn_w1, gin_w1, gcn_w2, gin_w2);

    // layer 1
    k_agg1<<<gW, 256>>>(X, N);
    k_tgemm_l1<<<2 * gG, 256>>>(gcn_b1, gin_b1, out, N, gG);

    // layer 2
    k_agg2<<<gW, 256>>>(N);
    k_tgemm_l2<<<gG, 256>>>(out, N);
    k_tgemm_fin<<<gG, 256>>>(out, N);
}

// round 9
// speedup vs baseline: 1.4911x; 1.1531x over previous
#include <cuda_runtime.h>
#include <cuda_bf16.h>
#include <cstdint>

#define DD 128
#define NMAX 100000
#define EMAX 1600000

// ---------------- static scratch ----------------
__device__ int   g_cnt[NMAX];
__device__ int   g_rowptr[NMAX + 1];
__device__ int   g_col[EMAX];
__device__ __align__(16) float g_dinv[NMAX];
__device__ int   g_blocksums[256];
__device__ __align__(16) float g_M[DD * DD];     // lin@fc
__device__ __align__(16) float g_Wg[DD * DD];    // gcn_w2 @ M
__device__ __align__(16) float g_Wn2[DD * DD];   // gin_w2 @ M
__device__ __align__(16) float g_Wn[DD * DD];    // gin_w1 @ gin_w2 @ M
__device__ __align__(16) float g_c0a[DD];        // 2*lin_b@fc + fc_b
__device__ __align__(16) float g_c0[DD];         // (b2+b2g)@M + c0a
__device__ __align__(16) float g_c1[DD];         // gin_b1 @ Wn2
// bf16 weight images [matrix][hi/lo], [n][k] layout: 0=gcn_w1, 1=Wg, 2=Wn
__device__ __align__(16) unsigned short g_wimg[3][2][16384];
// split panels (value = hi + lo): 0=aggW(X)/aggW(h), 1=A1=X+aggU(X), 2=h, 3=A2
__device__ __align__(16) unsigned short g_Ph[4][(size_t)NMAX * DD];
__device__ __align__(16) unsigned short g_Pl[4][(size_t)NMAX * DD];

// ---------------- PTX helpers ----------------
__device__ __forceinline__ uint32_t smem_u32(const void* p) {
    uint32_t a;
    asm("{ .reg .u64 t; cvta.to.shared.u64 t, %1; cvt.u32.u64 %0, t; }" : "=r"(a) : "l"(p));
    return a;
}
__device__ __forceinline__ void ldsm4(uint32_t* r, uint32_t addr) {
    asm volatile("ldmatrix.sync.aligned.m8n8.x4.shared.b16 {%0,%1,%2,%3}, [%4];"
                 : "=r"(r[0]), "=r"(r[1]), "=r"(r[2]), "=r"(r[3]) : "r"(addr));
}
__device__ __forceinline__ void mma_bf16(float* c, const uint32_t* a, const uint32_t* b) {
    asm volatile("mma.sync.aligned.m16n8k16.row.col.f32.bf16.bf16.f32 "
                 "{%0,%1,%2,%3}, {%4,%5,%6,%7}, {%8,%9}, {%0,%1,%2,%3};"
                 : "+f"(c[0]), "+f"(c[1]), "+f"(c[2]), "+f"(c[3])
                 : "r"(a[0]), "r"(a[1]), "r"(a[2]), "r"(a[3]), "r"(b[0]), "r"(b[1]));
}
__device__ __forceinline__ void cpasync16(uint32_t dst, const void* src, int szbytes) {
    asm volatile("cp.async.cg.shared.global [%0], [%1], 16, %2;"
                 :: "r"(dst), "l"(src), "r"(szbytes) : "memory");
}
__device__ __forceinline__ void cp_commit() { asm volatile("cp.async.commit_group;" ::: "memory"); }
template <int N> __device__ __forceinline__ void cp_wait() {
    asm volatile("cp.async.wait_group %0;" :: "n"(N) : "memory");
}
// conflict-free chunk16 tile: row r (0..127) of 16 bf16 = 2x16B octets, stride 32B
__device__ __forceinline__ uint32_t swz(int r, int p) {
    return (uint32_t)(r * 32 + ((p ^ (r & 1) ^ ((r >> 2) & 1)) << 4));
}
__device__ __forceinline__ void split4(float4 v, uint2& h, uint2& l) {
    __nv_bfloat16 h0 = __float2bfloat16(v.x), h1 = __float2bfloat16(v.y);
    __nv_bfloat16 h2 = __float2bfloat16(v.z), h3 = __float2bfloat16(v.w);
    __nv_bfloat16 l0 = __float2bfloat16(v.x - __bfloat162float(h0));
    __nv_bfloat16 l1 = __float2bfloat16(v.y - __bfloat162float(h1));
    __nv_bfloat16 l2 = __float2bfloat16(v.z - __bfloat162float(h2));
    __nv_bfloat16 l3 = __float2bfloat16(v.w - __bfloat162float(h3));
    h.x = (uint32_t)__bfloat16_as_ushort(h0) | ((uint32_t)__bfloat16_as_ushort(h1) << 16);
    h.y = (uint32_t)__bfloat16_as_ushort(h2) | ((uint32_t)__bfloat16_as_ushort(h3) << 16);
    l.x = (uint32_t)__bfloat16_as_ushort(l0) | ((uint32_t)__bfloat16_as_ushort(l1) << 16);
    l.y = (uint32_t)__bfloat16_as_ushort(l2) | ((uint32_t)__bfloat16_as_ushort(l3) << 16);
}
__device__ __forceinline__ float4 load_split4(const unsigned short* ph, const unsigned short* pl,
                                              size_t idx) {
    uint2 h = *(const uint2*)(ph + idx);
    uint2 l = *(const uint2*)(pl + idx);
    float4 r;
    r.x = __uint_as_float(h.x << 16) + __uint_as_float(l.x << 16);
    r.y = __uint_as_float(h.x & 0xFFFF0000u) + __uint_as_float(l.x & 0xFFFF0000u);
    r.z = __uint_as_float(h.y << 16) + __uint_as_float(l.y << 16);
    r.w = __uint_as_float(h.y & 0xFFFF0000u) + __uint_as_float(l.y & 0xFFFF0000u);
    return r;
}

// ---------------- CSR build ----------------
__global__ void k_zero_cnt(int n) {
    int i = blockIdx.x * blockDim.x + threadIdx.x;
    if (i < n) g_cnt[i] = 0;
}
__global__ void k_hist(const int* __restrict__ ei, int E, int n) {
    int e = blockIdx.x * blockDim.x + threadIdx.x;
    if (e < E) {
        int d = ei[E + e];
        if (d >= 0 && d < n) atomicAdd(&g_cnt[d], 1);
    }
}
__global__ void k_scan1(int n) {
    __shared__ int s[1024];
    int i = blockIdx.x * 1024 + threadIdx.x;
    int v = (i < n) ? g_cnt[i] : 0;
    s[threadIdx.x] = v;
    __syncthreads();
    for (int off = 1; off < 1024; off <<= 1) {
        int t = (threadIdx.x >= off) ? s[threadIdx.x - off] : 0;
        __syncthreads();
        s[threadIdx.x] += t;
        __syncthreads();
    }
    if (i < n) g_rowptr[i] = s[threadIdx.x] - v;
    if (threadIdx.x == 1023) g_blocksums[blockIdx.x] = s[1023];
}
__global__ void k_scan2(int nb) {
    __shared__ int s[256];
    int t = threadIdx.x;
    int v = (t < nb) ? g_blocksums[t] : 0;
    s[t] = v;
    __syncthreads();
    for (int off = 1; off < 256; off <<= 1) {
        int u = (t >= off) ? s[t - off] : 0;
        __syncthreads();
        s[t] += u;
        __syncthreads();
    }
    if (t < nb) g_blocksums[t] = s[t] - v;
}
__global__ void k_scan3(int n, int E) {
    int i = blockIdx.x * blockDim.x + threadIdx.x;
    if (i < n) {
        g_rowptr[i] += g_blocksums[i >> 10];
        g_dinv[i] = rsqrtf((float)g_cnt[i] + 1.0f);
        g_cnt[i] = 0;
    }
    if (i == 0) g_rowptr[n] = E;
}
__global__ void k_fill(const int* __restrict__ ei, int E, int n) {
    int e = blockIdx.x * blockDim.x + threadIdx.x;
    if (e < E) {
        int s = ei[e];
        int d = ei[E + e];
        if (s >= 0 && s < n && d >= 0 && d < n) {
            int pos = g_rowptr[d] + atomicAdd(&g_cnt[d], 1);
            g_col[pos] = s;
        }
    }
}
// NOTE: after k_fill, g_cnt[i] == incoming degree again (used by l2 epilogue).

// ---------------- weight-folding precompute (128^3 each, tiny) ----------------
__global__ void k_pre1(const float* __restrict__ lin_w, const float* __restrict__ lin_b,
                       const float* __restrict__ fc_w, const float* __restrict__ fc_b) {
    int c = threadIdx.x;
    if (blockIdx.x < DD) {
        int r = blockIdx.x;
        float a = 0.f;
        #pragma unroll 8
        for (int k = 0; k < DD; k++) a += lin_w[r * DD + k] * fc_w[k * DD + c];
        g_M[r * DD + c] = a;
    } else {
        float a = 0.f;
        #pragma unroll 8
        for (int k = 0; k < DD; k++) a += lin_b[k] * fc_w[k * DD + c];
        g_c0a[c] = 2.f * a + fc_b[c];
    }
}
__global__ void k_pre2(const float* __restrict__ gcn_w2, const float* __restrict__ gin_w2,
                       const float* __restrict__ gcn_b2, const float* __restrict__ gin_b2) {
    int c = threadIdx.x;
    if (blockIdx.x < DD) {
        int r = blockIdx.x;
        float a = 0.f, b = 0.f;
        #pragma unroll 8
        for (int k = 0; k < DD; k++) {
            float m = g_M[k * DD + c];
            a += gcn_w2[r * DD + k] * m;
            b += gin_w2[r * DD + k] * m;
        }
        g_Wg[r * DD + c] = a;
        g_Wn2[r * DD + c] = b;
    } else {
        float a = 0.f;
        #pragma unroll 8
        for (int k = 0; k < DD; k++)
            a += (gcn_b2[k] + gin_b2[k]) * g_M[k * DD + c];
        g_c0[c] = a + g_c0a[c];
    }
}
__global__ void k_pre3(const float* __restrict__ gin_w1, const float* __restrict__ gin_b1) {
    int c = threadIdx.x;
    if (blockIdx.x < DD) {
        int r = blockIdx.x;
        float a = 0.f;
        #pragma unroll 8
        for (int k = 0; k < DD; k++) a += gin_w1[r * DD + k] * g_Wn2[k * DD + c];
        g_Wn[r * DD + c] = a;
    } else {
        float a = 0.f;
        #pragma unroll 8
        for (int k = 0; k < DD; k++) a += gin_b1[k] * g_Wn2[k * DD + c];
        g_c1[c] = a;
    }
}

// ---------------- weight prep: fp32 [k][n] -> bf16 hi/lo in [n][k] ----------------
__global__ void k_wprep(const float* __restrict__ gcn_w1) {
    int mat = blockIdx.y;
    int i = blockIdx.x * 256 + threadIdx.x;
    if (i >= 16384) return;
    int k = i >> 7, nn = i & 127;
    const float* W = (mat == 0) ? gcn_w1 : (mat == 1) ? g_Wg : g_Wn;
    float x = W[k * 128 + nn];
    __nv_bfloat16 hi = __float2bfloat16(x);
    __nv_bfloat16 lo = __float2bfloat16(x - __bfloat162float(hi));
    g_wimg[mat][0][nn * 128 + k] = __bfloat16_as_ushort(hi);
    g_wimg[mat][1][nn * 128 + k] = __bfloat16_as_ushort(lo);
}

// ---------------- aggregation (warp per node, batched edges, split IO) ----------------
// pass1: P0 = aggW(X)+self, P1 = A1 = X + aggU(X)
__global__ void k_agg1(const float* __restrict__ X, int n) {
    int w = (blockIdx.x * blockDim.x + threadIdx.x) >> 5;
    if (w >= n) return;
    int lane = threadIdx.x & 31;
    const float4* Xv = (const float4*)X;
    int e = g_rowptr[w], end = g_rowptr[w + 1];
    float4 aw = make_float4(0, 0, 0, 0), au = make_float4(0, 0, 0, 0);
    for (; e + 4 <= end; e += 4) {
        int j0 = g_col[e], j1 = g_col[e + 1], j2 = g_col[e + 2], j3 = g_col[e + 3];
        float d0 = g_dinv[j0], d1 = g_dinv[j1], d2 = g_dinv[j2], d3 = g_dinv[j3];
        float4 v0 = Xv[(size_t)j0 * 32 + lane];
        float4 v1 = Xv[(size_t)j1 * 32 + lane];
        float4 v2 = Xv[(size_t)j2 * 32 + lane];
        float4 v3 = Xv[(size_t)j3 * 32 + lane];
        aw.x += d0 * v0.x + d1 * v1.x + d2 * v2.x + d3 * v3.x;
        aw.y += d0 * v0.y + d1 * v1.y + d2 * v2.y + d3 * v3.y;
        aw.z += d0 * v0.z + d1 * v1.z + d2 * v2.z + d3 * v3.z;
        aw.w += d0 * v0.w + d1 * v1.w + d2 * v2.w + d3 * v3.w;
        au.x += v0.x + v1.x + v2.x + v3.x;
        au.y += v0.y + v1.y + v2.y + v3.y;
        au.z += v0.z + v1.z + v2.z + v3.z;
        au.w += v0.w + v1.w + v2.w + v3.w;
    }
    for (; e < end; e++) {
        int j = g_col[e];
        float dj = g_dinv[j];
        float4 v = Xv[(size_t)j * 32 + lane];
        aw.x += dj * v.x; aw.y += dj * v.y; aw.z += dj * v.z; aw.w += dj * v.w;
        au.x += v.x;      au.y += v.y;      au.z += v.z;      au.w += v.w;
    }
    float di = g_dinv[w], dii = di * di;
    float4 xi = Xv[(size_t)w * 32 + lane];
    float4 ow, ou;
    ow.x = di * aw.x + dii * xi.x; ow.y = di * aw.y + dii * xi.y;
    ow.z = di * aw.z + dii * xi.z; ow.w = di * aw.w + dii * xi.w;
    ou.x = au.x + xi.x; ou.y = au.y + xi.y; ou.z = au.z + xi.z; ou.w = au.w + xi.w;
    size_t idx = (size_t)w * 128 + lane * 4;
    uint2 h, l;
    split4(ow, h, l);
    *(uint2*)&g_Ph[0][idx] = h;  *(uint2*)&g_Pl[0][idx] = l;
    split4(ou, h, l);
    *(uint2*)&g_Ph[1][idx] = h;  *(uint2*)&g_Pl[1][idx] = l;
}
// pass2: P0 = aggW(P2=h)+self, P3 = A2 = P1 + aggU(P1)
__global__ void k_agg2(int n) {
    int w = (blockIdx.x * blockDim.x + threadIdx.x) >> 5;
    if (w >= n) return;
    int lane = threadIdx.x & 31;
    int e = g_rowptr[w], end = g_rowptr[w + 1];
    float4 aw = make_float4(0, 0, 0, 0), au = make_float4(0, 0, 0, 0);
    for (; e + 2 <= end; e += 2) {
        int j0 = g_col[e], j1 = g_col[e + 1];
        float d0 = g_dinv[j0], d1 = g_dinv[j1];
        size_t i0 = (size_t)j0 * 128 + lane * 4, i1 = (size_t)j1 * 128 + lane * 4;
        float4 h0 = load_split4(g_Ph[2], g_Pl[2], i0);
        float4 h1 = load_split4(g_Ph[2], g_Pl[2], i1);
        float4 a0 = load_split4(g_Ph[1], g_Pl[1], i0);
        float4 a1 = load_split4(g_Ph[1], g_Pl[1], i1);
        aw.x += d0 * h0.x + d1 * h1.x; aw.y += d0 * h0.y + d1 * h1.y;
        aw.z += d0 * h0.z + d1 * h1.z; aw.w += d0 * h0.w + d1 * h1.w;
        au.x += a0.x + a1.x; au.y += a0.y + a1.y;
        au.z += a0.z + a1.z; au.w += a0.w + a1.w;
    }
    for (; e < end; e++) {
        int j = g_col[e];
        float dj = g_dinv[j];
        size_t i0 = (size_t)j * 128 + lane * 4;
        float4 hv = load_split4(g_Ph[2], g_Pl[2], i0);
        float4 av = load_split4(g_Ph[1], g_Pl[1], i0);
        aw.x += dj * hv.x; aw.y += dj * hv.y; aw.z += dj * hv.z; aw.w += dj * hv.w;
        au.x += av.x;      au.y += av.y;      au.z += av.z;      au.w += av.w;
    }
    float di = g_dinv[w], dii = di * di;
    size_t iw = (size_t)w * 128 + lane * 4;
    float4 hi = load_split4(g_Ph[2], g_Pl[2], iw);
    float4 ai = load_split4(g_Ph[1], g_Pl[1], iw);
    float4 ow, ou;
    ow.x = di * aw.x + dii * hi.x; ow.y = di * aw.y + dii * hi.y;
    ow.z = di * aw.z + dii * hi.z; ow.w = di * aw.w + dii * hi.w;
    ou.x = au.x + ai.x; ou.y = au.y + ai.y; ou.z = au.z + ai.z; ou.w = au.w + ai.w;
    uint2 h, l;
    split4(ow, h, l);
    *(uint2*)&g_Ph[0][iw] = h;  *(uint2*)&g_Pl[0][iw] = l;
    split4(ou, h, l);
    *(uint2*)&g_Ph[3][iw] = h;  *(uint2*)&g_Pl[3][iw] = l;
}

// ---------------- pipelined warp-mma split GEMM ----------------
// C_tile[128,128] = sum_pass A_pass @ W_pass; split terms Ah*Wh + Al*Wh + Ah*Wl.
// K chunks of 16; 2-stage cp.async double buffer; 8 warps = 4(m) x 2(n), warp 32x64.
// BSEL: 0 = bias_param, 3 = deg-scaled (out += (cnt+1)*c1 + c0).
template <bool RELU, bool DUAL, int INA1, int INA2, int OUTI, int W1I, int W2I,
          int BSEL, bool OUTF32>
__device__ __forceinline__ void tgemm_body(int bx, const float* bias_param,
                                           float* outp, int n, uint32_t sbase) {
    int tid = threadIdx.x, lane = tid & 31, wid = tid >> 5;
    int wm = wid & 3, wn = wid >> 2;
    int row0 = bx * 128;

    float acc[2][8][4];
    #pragma unroll
    for (int i = 0; i < 2; i++)
        #pragma unroll
        for (int j = 0; j < 8; j++)
            #pragma unroll
            for (int q = 0; q < 4; q++) acc[i][j][q] = 0.f;

    const int T = DUAL ? 16 : 8;
    int sr = tid >> 1, sp = tid & 1;
    uint32_t soff = swz(sr, sp);
    int sgr = row0 + sr;
    bool svalid = sgr < n;
    size_t s_asrc = (size_t)(svalid ? sgr : 0) * 128 + sp * 8;
    size_t s_wsrc = (size_t)sr * 128 + sp * 8;

    auto do_stage = [&](int c) {
        int pass = DUAL ? (c >> 3) : 0;
        int kc = c & 7, s = c & 1;
        const unsigned short* Ah = g_Ph[pass ? INA2 : INA1];
        const unsigned short* Al = g_Pl[pass ? INA2 : INA1];
        int wi = pass ? W2I : W1I;
        uint32_t b = sbase + s * 16384;
        size_t ka = s_asrc + kc * 16, kw = s_wsrc + kc * 16;
        cpasync16(b + soff,         Ah + ka, svalid ? 16 : 0);
        cpasync16(b + 4096 + soff,  Al + ka, svalid ? 16 : 0);
        cpasync16(b + 8192 + soff,  g_wimg[wi][0] + kw, 16);
        cpasync16(b + 12288 + soff, g_wimg[wi][1] + kw, 16);
    };

    do_stage(0);
    cp_commit();

    for (int c = 0; c < T; c++) {
        if (c + 1 < T) {
            do_stage(c + 1);
            cp_commit();
            cp_wait<1>();
        } else {
            cp_wait<0>();
        }
        __syncthreads();

        uint32_t b0 = sbase + (c & 1) * 16384;
        #pragma unroll
        for (int term = 0; term < 3; term++) {
            uint32_t ab = b0 + ((term == 1) ? 4096 : 0);
            uint32_t wb = b0 + 8192 + ((term == 2) ? 4096 : 0);
            uint32_t a[2][4], bf[8][2];
            #pragma unroll
            for (int mi = 0; mi < 2; mi++) {
                int row = wm * 32 + mi * 16 + (lane & 15);
                ldsm4(a[mi], ab + swz(row, lane >> 4));
            }
            #pragma unroll
            for (int q = 0; q < 4; q++) {
                int rown = wn * 64 + q * 16 + ((lane >> 4) << 3) + (lane & 7);
                uint32_t r4[4];
                ldsm4(r4, wb + swz(rown, (lane >> 3) & 1));
                bf[q * 2 + 0][0] = r4[0]; bf[q * 2 + 0][1] = r4[1];
                bf[q * 2 + 1][0] = r4[2]; bf[q * 2 + 1][1] = r4[3];
            }
            #pragma unroll
            for (int mi = 0; mi < 2; mi++)
                #pragma unroll
                for (int nj = 0; nj < 8; nj++)
                    mma_bf16(acc[mi][nj], a[mi], bf[nj]);
        }
        __syncthreads();
    }

    // epilogue
    int rbase = row0 + wm * 32 + (lane >> 2);
    int cbase = wn * 64 + (lane & 3) * 2;
    #pragma unroll
    for (int mi = 0; mi < 2; mi++) {
        #pragma unroll
        for (int half = 0; half < 2; half++) {
            int gr = rbase + mi * 16 + half * 8;
            if (gr >= n) continue;
            float s = (BSEL == 3) ? (float)(g_cnt[gr] + 1) : 0.f;
            #pragma unroll
            for (int nj = 0; nj < 8; nj++) {
                int col = cbase + nj * 8;
                float v0, v1;
                if (BSEL == 3) {
                    v0 = acc[mi][nj][half * 2 + 0] + s * g_c1[col]     + g_c0[col];
                    v1 = acc[mi][nj][half * 2 + 1] + s * g_c1[col + 1] + g_c0[col + 1];
                } else {
                    v0 = acc[mi][nj][half * 2 + 0] + bias_param[col];
                    v1 = acc[mi][nj][half * 2 + 1] + bias_param[col + 1];
                }
                if (RELU) { v0 = fmaxf(v0, 0.f); v1 = fmaxf(v1, 0.f); }
                if (OUTF32) {
                    *(float2*)&outp[(size_t)gr * 128 + col] = make_float2(v0, v1);
                } else {
                    __nv_bfloat16 h0 = __float2bfloat16(v0), h1 = __float2bfloat16(v1);
                    __nv_bfloat16 l0 = __float2bfloat16(v0 - __bfloat162float(h0));
                    __nv_bfloat16 l1 = __float2bfloat16(v1 - __bfloat162float(h1));
                    size_t o = (size_t)gr * 128 + col;
                    *(uint32_t*)&g_Ph[OUTI][o] =
                        (uint32_t)__bfloat16_as_ushort(h0) | ((uint32_t)__bfloat16_as_ushort(h1) << 16);
                    *(uint32_t*)&g_Pl[OUTI][o] =
                        (uint32_t)__bfloat16_as_ushort(l0) | ((uint32_t)__bfloat16_as_ushort(l1) << 16);
                }
            }
        }
    }
}

// layer-1 GCN only: h = relu(P0 @ gcn_w1 + b1) -> P2 split
__global__ void __launch_bounds__(256, 2) k_tgemm_l1(const float* __restrict__ b1,
                                                     float* __restrict__ outp, int n) {
    __shared__ __align__(1024) unsigned char sbuf[2 * 4 * 4096];
    tgemm_body<true, false, 0, 0, 2, 0, 0, 0, false>(blockIdx.x, b1, outp, n, smem_u32(sbuf));
}
// layer-2 fused head: out = P0@Wg + P3@Wn + (cnt+1)*c1 + c0   (fp32 out)
__global__ void __launch_bounds__(256, 2) k_tgemm_l2(float* __restrict__ outp, int n) {
    __shared__ __align__(1024) unsigned char sbuf[2 * 4 * 4096];
    tgemm_body<false, true, 0, 3, 0, 1, 2, 3, true>(blockIdx.x, outp, outp, n, smem_u32(sbuf));
}

// ---------------- launch ----------------
extern "C" void kernel_launch(void* const* d_in, const int* in_sizes, int n_in,
                              void* d_out, int out_size) {
    const float* X      = (const float*)d_in[0];
    const int*   ei     = (const int*)d_in[1];
    const float* gcn_w1 = (const float*)d_in[2];
    const float* gcn_b1 = (const float*)d_in[3];
    const float* gcn_w2 = (const float*)d_in[4];
    const float* gcn_b2 = (const float*)d_in[5];
    const float* gin_w1 = (const float*)d_in[6];
    const float* gin_b1 = (const float*)d_in[7];
    const float* gin_w2 = (const float*)d_in[8];
    const float* gin_b2 = (const float*)d_in[9];
    const float* lin_w  = (const float*)d_in[10];
    const float* lin_b  = (const float*)d_in[11];
    const float* fc_w   = (const float*)d_in[12];
    const float* fc_b   = (const float*)d_in[13];
    float*       out    = (float*)d_out;

    int N = in_sizes[0] / DD;
    int E = in_sizes[1] / 2;

    int nb = (N + 1023) / 1024;
    int gN = (N + 255) / 256;
    int gE = (E + 255) / 256;
    int gW = (N + 7) / 8;
    int gG = (N + 127) / 128;

    // CSR build (after k_fill, g_cnt holds incoming degree again)
    k_zero_cnt<<<gN, 256>>>(N);
    k_hist<<<gE, 256>>>(ei, E, N);
    k_scan1<<<nb, 1024>>>(N);
    k_scan2<<<1, 256>>>(nb);
    k_scan3<<<gN, 256>>>(N, E);
    k_fill<<<gE, 256>>>(ei, E, N);

    // weight folding: M -> {Wg, Wn2, c0} -> {Wn, c1}; then bf16 images
    k_pre1<<<DD + 1, DD>>>(lin_w, lin_b, fc_w, fc_b);
    k_pre2<<<DD + 1, DD>>>(gcn_w2, gin_w2, gcn_b2, gin_b2);
    k_pre3<<<DD + 1, DD>>>(gin_w1, gin_b1);
    k_wprep<<<dim3(64, 3), 256>>>(gcn_w1);

    // layer 1: single shared aggregation; only the GCN branch needs a GEMM
    k_agg1<<<gW, 256>>>(X, N);
    k_tgemm_l1<<<gG, 256>>>(gcn_b1, out, N);

    // layer 2: aggregate h (weighted) and A1 (unweighted), then one dual GEMM to out
    k_agg2<<<gW, 256>>>(N);
    k_tgemm_l2<<<gG, 256>>>(out, N);
}